// round 4
// baseline (speedup 1.0000x reference)
#include <cuda_runtime.h>
#include <cuda_bf16.h>
#include <mma.h>
#include <cstdint>

using namespace nvcuda;
typedef __nv_bfloat16 bf16;

#define BB   128
#define NN   36
#define FEATD 2048
#define MIDD 517
#define HIDD 128
#define OUTD 1024
#define G4   4096
#define KP2  576
#define TSTEPS 36
#define NBLK_LSTM 128

// ---- tf32 core geometry (128x64 tile) ----
#define F_LD 36
#define F_ABYTES (128 * F_LD * 4)          // 18432
#define F_BBYTES (64 * F_LD * 4)           // 9216
#define F_STAGE  (F_ABYTES + F_BBYTES)     // 27648
#define F_DYN    (3 * F_STAGE)             // 82944

// ---- bf16x3 core geometry (64x64 tile) ----
#define H_LD 40
#define H_MAT   (64 * H_LD * 2)            // 5120
#define H_STAGE (4 * H_MAT)                // 20480
#define H_DYN   (3 * H_STAGE)              // 61440

// ------------------------- scratch -------------------------
__device__ float g_scale[BB];
__device__ float g_sigatt[BB * NN];
__device__ float g_feats[BB * MIDD * NN];              // [b][m][n]
__device__ float g_hx[BB * HIDD * NN];
__device__ float g_hy[BB * HIDD * NN];
__device__ __align__(16) float g_xseq[(size_t)TSTEPS * BB * KP2];   // [t*128+b][k]
__device__ __align__(16) float g_wih_f[(size_t)G4 * KP2];           // col = u*4+g
__device__ float g_gates_in[(size_t)TSTEPS * BB * G4];              // reordered cols
__device__ __align__(16) bf16 g_whh_hi[(size_t)G4 * OUTD];          // reordered rows
__device__ __align__(16) bf16 g_whh_lo[(size_t)G4 * OUTD];
__device__ __align__(16) bf16 g_hhi0[BB * OUTD];
__device__ __align__(16) bf16 g_hlo0[BB * OUTD];
__device__ __align__(16) bf16 g_hhi1[BB * OUTD];
__device__ __align__(16) bf16 g_hlo1[BB * OUTD];
__device__ float g_c[BB * OUTD];
__device__ unsigned g_cnt;                 // persistent-kernel barrier counter

// ------------------------- helpers -------------------------
__device__ __forceinline__ void split_write(float v, bf16* hi, bf16* lo) {
    bf16 h = __float2bfloat16(v);
    *hi = h;
    *lo = __float2bfloat16(v - __bfloat162float(h));
}

__device__ __forceinline__ void cp16(void* dst, const void* src) {
    unsigned d = (unsigned)__cvta_generic_to_shared(dst);
    asm volatile("cp.async.ca.shared.global [%0], [%1], 16;\n" ::"r"(d), "l"(src));
}
// L2-coherent variant (bypass L1) for cross-SM-communicated data (h state)
__device__ __forceinline__ void cp16cg(void* dst, const void* src) {
    unsigned d = (unsigned)__cvta_generic_to_shared(dst);
    asm volatile("cp.async.cg.shared.global [%0], [%1], 16;\n" ::"r"(d), "l"(src));
}

// ------------------------- prep kernels -------------------------
__global__ void k_init() {
    int idx = blockIdx.x * blockDim.x + threadIdx.x;
    if (idx == 0) g_cnt = 0;
    if (idx >= BB * OUTD) return;
    g_hhi0[idx] = __float2bfloat16(0.f);
    g_hlo0[idx] = __float2bfloat16(0.f);
    g_c[idx] = 0.f;
}

__global__ void k_scale(const float* __restrict__ boxes) {
    int b = blockIdx.x * blockDim.x + threadIdx.x;
    if (b >= BB) return;
    const float* p = boxes + (size_t)b * 4 * NN;
    float m = -1e30f;
    for (int i = 0; i < 4 * NN; i++) m = fmaxf(m, p[i]);
    g_scale[b] = m;
}

__global__ void k_head(const float* __restrict__ boxes,
                       const float* __restrict__ att) {
    int idx = blockIdx.x * blockDim.x + threadIdx.x;
    if (idx >= BB * NN) return;
    int b = idx / NN, n = idx - b * NN;
    float inv = 1.f / g_scale[b];
    for (int r = 0; r < 4; r++)
        g_feats[(size_t)b * MIDD * NN + r * NN + n] =
            boxes[(size_t)b * 4 * NN + r * NN + n] * inv;
    float a = att[idx];
    g_feats[(size_t)b * MIDD * NN + 4 * NN + n] = a;
    g_sigatt[idx] = 1.f / (1.f + expf(-a));
}

__global__ void k_pad_wih(const float* __restrict__ wih) {
    size_t idx = (size_t)blockIdx.x * blockDim.x + threadIdx.x;
    if (idx >= (size_t)G4 * KP2) return;
    int cr = (int)(idx / KP2), k = (int)(idx - (size_t)cr * KP2);
    int u = cr >> 2, g = cr & 3;
    g_wih_f[idx] = (k < MIDD) ? wih[(size_t)(g * OUTD + u) * MIDD + k] : 0.f;
}

__global__ void k_split_whh(const float* __restrict__ whh) {
    size_t idx = (size_t)blockIdx.x * blockDim.x + threadIdx.x;
    if (idx >= (size_t)G4 * OUTD) return;
    int cr = (int)(idx / OUTD), k = (int)(idx - (size_t)cr * OUTD);
    int u = cr >> 2, g = cr & 3;
    float v = whh[(size_t)(g * OUTD + u) * OUTD + k];
    split_write(v, &g_whh_hi[idx], &g_whh_lo[idx]);
}

// ------------------------- TF32 core: 128x64 tile, 256 thr ------------------
// C = A[m0:+128,:K] * B[n0:+64,:K]^T (both row-major K-contiguous fp32)
__device__ __forceinline__ float* gemm_tf32(
    const float* __restrict__ A, const float* __restrict__ B,
    int lda, int ldb, int nch, int m0, int n0, char* sm)
{
    const int t = threadIdx.x, w = t >> 5;

    wmma::fragment<wmma::accumulator, 16, 16, 8, float> acc[4];
#pragma unroll
    for (int j = 0; j < 4; j++) wmma::fill_fragment(acc[j], 0.f);

    auto issue = [&](int jc) {
        char* st = sm + (jc % 3) * F_STAGE;
        int k0 = jc * 32;
#pragma unroll
        for (int u = 0; u < 6; u++) {
            int seg = t + u * 256;
            const float* src;
            char* dst;
            if (seg < 1024) {
                int row = seg >> 3, s = seg & 7;
                src = A + (size_t)(m0 + row) * lda + k0 + s * 4;
                dst = st + row * (F_LD * 4) + s * 16;
            } else {
                int x = seg - 1024;
                int row = x >> 3, s = x & 7;
                src = B + (size_t)(n0 + row) * ldb + k0 + s * 4;
                dst = st + F_ABYTES + row * (F_LD * 4) + s * 16;
            }
            cp16(dst, src);
        }
        asm volatile("cp.async.commit_group;\n" ::: "memory");
    };

    issue(0);
    issue(1);
    for (int i = 0; i < nch; i++) {
        if (i < nch - 1)
            asm volatile("cp.async.wait_group 1;\n" ::: "memory");
        else
            asm volatile("cp.async.wait_group 0;\n" ::: "memory");
        __syncthreads();
        if (i + 2 < nch) issue(i + 2);

        char* st = sm + (i % 3) * F_STAGE;
        float* As = (float*)st;
        float* Bs = (float*)(st + F_ABYTES);
#pragma unroll
        for (int ks = 0; ks < 4; ks++) {
            int kk = ks * 8;
            wmma::fragment<wmma::matrix_a, 16, 16, 8, wmma::precision::tf32,
                           wmma::row_major> af;
            wmma::load_matrix_sync(af, &As[(w * 16) * F_LD + kk], F_LD);
#pragma unroll
            for (int e = 0; e < af.num_elements; e++)
                af.x[e] = wmma::__float_to_tf32(af.x[e]);
#pragma unroll
            for (int j = 0; j < 4; j++) {
                wmma::fragment<wmma::matrix_b, 16, 16, 8, wmma::precision::tf32,
                               wmma::col_major> bf;
                wmma::load_matrix_sync(bf, &Bs[(j * 16) * F_LD + kk], F_LD);
#pragma unroll
                for (int e = 0; e < bf.num_elements; e++)
                    bf.x[e] = wmma::__float_to_tf32(bf.x[e]);
                wmma::mma_sync(acc[j], af, bf, acc[j]);
            }
        }
    }
    __syncthreads();
    float* Cs = (float*)sm;   // 128*64*4 = 32KB, aliases stages 0-1 (consumed)
#pragma unroll
    for (int j = 0; j < 4; j++)
        wmma::store_matrix_sync(&Cs[(w * 16) * 64 + j * 16], acc[j], 64,
                                wmma::mem_row_major);
    __syncthreads();
    return Cs;
}

// ------------------------- bf16x3 core: 64x64 tile, 256 thr -----------------
__device__ __forceinline__ float* gemm_bf16x3(
    const bf16* __restrict__ Ahi, const bf16* __restrict__ Alo,
    const bf16* __restrict__ Bhi, const bf16* __restrict__ Blo,
    int lda, int ldb, int nch, int m0, int n0, char* sm)
{
    const int t = threadIdx.x, w = t >> 5;
    const int wm = w >> 1, wn = w & 1;

    wmma::fragment<wmma::accumulator, 16, 16, 16, float> acc[2];
    wmma::fill_fragment(acc[0], 0.f);
    wmma::fill_fragment(acc[1], 0.f);

    auto issue = [&](int jc) {
        char* st = sm + (jc % 3) * H_STAGE;
        int k0 = jc * 32;
#pragma unroll
        for (int u = 0; u < 4; u++) {
            int seg = t + u * 256;
            int mat = seg >> 8;
            int x = seg & 255;
            int row = x >> 2, s = x & 3;
            char* dst = st + mat * H_MAT + row * (H_LD * 2) + s * 16;
            if (mat == 0)
                cp16cg(dst, Ahi + (size_t)(m0 + row) * lda + k0 + s * 8);
            else if (mat == 1)
                cp16cg(dst, Alo + (size_t)(m0 + row) * lda + k0 + s * 8);
            else if (mat == 2)
                cp16(dst, Bhi + (size_t)(n0 + row) * ldb + k0 + s * 8);
            else
                cp16(dst, Blo + (size_t)(n0 + row) * ldb + k0 + s * 8);
        }
        asm volatile("cp.async.commit_group;\n" ::: "memory");
    };

    issue(0);
    issue(1);
    for (int i = 0; i < nch; i++) {
        if (i < nch - 1)
            asm volatile("cp.async.wait_group 1;\n" ::: "memory");
        else
            asm volatile("cp.async.wait_group 0;\n" ::: "memory");
        __syncthreads();
        if (i + 2 < nch) issue(i + 2);

        char* st = sm + (i % 3) * H_STAGE;
        bf16* sAhi = (bf16*)st;
        bf16* sAlo = (bf16*)(st + H_MAT);
        bf16* sBhi = (bf16*)(st + 2 * H_MAT);
        bf16* sBlo = (bf16*)(st + 3 * H_MAT);
#pragma unroll
        for (int ks = 0; ks < 2; ks++) {
            const int kk = ks * 16;
            wmma::fragment<wmma::matrix_a, 16, 16, 16, bf16, wmma::row_major> ah, al;
            wmma::fragment<wmma::matrix_b, 16, 16, 16, bf16, wmma::col_major> bh0, bh1, bl0, bl1;
            wmma::load_matrix_sync(ah, &sAhi[(wm * 16) * H_LD + kk], H_LD);
            wmma::load_matrix_sync(al, &sAlo[(wm * 16) * H_LD + kk], H_LD);
            wmma::load_matrix_sync(bh0, &sBhi[(wn * 32) * H_LD + kk], H_LD);
            wmma::load_matrix_sync(bh1, &sBhi[(wn * 32 + 16) * H_LD + kk], H_LD);
            wmma::load_matrix_sync(bl0, &sBlo[(wn * 32) * H_LD + kk], H_LD);
            wmma::load_matrix_sync(bl1, &sBlo[(wn * 32 + 16) * H_LD + kk], H_LD);
            wmma::mma_sync(acc[0], ah, bh0, acc[0]);
            wmma::mma_sync(acc[1], ah, bh1, acc[1]);
            wmma::mma_sync(acc[0], ah, bl0, acc[0]);
            wmma::mma_sync(acc[1], ah, bl1, acc[1]);
            wmma::mma_sync(acc[0], al, bh0, acc[0]);
            wmma::mma_sync(acc[1], al, bh1, acc[1]);
        }
    }
    __syncthreads();
    float* Cs = (float*)sm;   // 16KB aliases stage0 (consumed)
    wmma::store_matrix_sync(&Cs[(wm * 16) * 64 + wn * 32], acc[0], 64,
                            wmma::mem_row_major);
    wmma::store_matrix_sync(&Cs[(wm * 16) * 64 + wn * 32 + 16], acc[1], 64,
                            wmma::mem_row_major);
    __syncthreads();
    return Cs;
}

// ------------------------- conv GEMM (TF32 single pass) ---------------------
__global__ __launch_bounds__(256) void k_conv(const float* __restrict__ convw,
                                              const float* __restrict__ feat,
                                              const float* __restrict__ convb) {
    extern __shared__ char sm[];
    int m0 = blockIdx.x * 128, n0 = blockIdx.y * 64;
    float* Cs = gemm_tf32(convw, feat, FEATD, FEATD, FEATD / 32, m0, n0, sm);
    for (int idx = threadIdx.x; idx < 128 * 64; idx += 256) {
        int r = idx >> 6, cc = idx & 63;
        int m = m0 + r, col = n0 + cc;
        int b = col / NN, n = col - b * NN;
        g_feats[(size_t)b * MIDD * NN + (5 + m) * NN + n] = Cs[idx] + convb[m];
    }
}

// ------------------------- input-gate GEMM (TF32 single pass) ---------------
__global__ __launch_bounds__(256) void k_gin(const float* __restrict__ bih,
                                             const float* __restrict__ bhh) {
    extern __shared__ char sm[];
    int m0 = blockIdx.x * 128, n0 = blockIdx.y * 64;
    float* Cs = gemm_tf32(g_xseq, g_wih_f, KP2, KP2, KP2 / 32, m0, n0, sm);
    for (int idx = threadIdx.x; idx < 128 * 64; idx += 256) {
        int r = idx >> 6, cc = idx & 63;
        int row = m0 + r, col = n0 + cc;
        int orig = (col & 3) * OUTD + (col >> 2);
        g_gates_in[(size_t)row * G4 + col] = Cs[idx] + bih[orig] + bhh[orig];
    }
}

// ------------------------- persistent fused LSTM ----------------------------
__global__ __launch_bounds__(256) void k_lstm(float* __restrict__ outc) {
    extern __shared__ char sm[];
    int bid = blockIdx.x;
    int b0 = (bid >> 6) * 64;
    int n0 = (bid & 63) * 64;

    for (int s = 0; s < TSTEPS; s++) {
        const bf16* hin_hi = (s & 1) ? g_hhi1 : g_hhi0;
        const bf16* hin_lo = (s & 1) ? g_hlo1 : g_hlo0;
        bf16* hout_hi = (s & 1) ? g_hhi0 : g_hhi1;
        bf16* hout_lo = (s & 1) ? g_hlo0 : g_hlo1;

        float* Cs = gemm_bf16x3(hin_hi, hin_lo, g_whh_hi, g_whh_lo,
                                OUTD, OUTD, OUTD / 32, b0, n0, sm);

        const float* gin = g_gates_in + (size_t)s * BB * G4;
        for (int p = threadIdx.x; p < 1024; p += 256) {
            int r = p >> 4, lu = p & 15;
            int b = b0 + r;
            int u = (n0 >> 2) + lu;
            float4 gv = *(const float4*)(gin + (size_t)b * G4 + n0 + lu * 4);
            const float* cr = &Cs[r * 64 + lu * 4];
            float ig = cr[0] + gv.x;
            float fg = cr[1] + gv.y;
            float gg = cr[2] + gv.z;
            float og = cr[3] + gv.w;
            float si = 1.f / (1.f + expf(-ig));
            float sf = 1.f / (1.f + expf(-fg));
            float so = 1.f / (1.f + expf(-og));
            int ci = b * OUTD + u;
            float c = sf * g_c[ci] + si * tanhf(gg);
            g_c[ci] = c;
            float h = so * tanhf(c);
            split_write(h, &hout_hi[ci], &hout_lo[ci]);
            if (s == TSTEPS - 1) outc[ci] = c;
        }

        // device-wide barrier (monotone counter; reset by k_init each launch)
        __threadfence();
        __syncthreads();
        if (threadIdx.x == 0) {
            atomicAdd(&g_cnt, 1u);
            unsigned tgt = (unsigned)NBLK_LSTM * (s + 1);
            while (*(volatile unsigned*)&g_cnt < tgt) __nanosleep(32);
            __threadfence();
        }
        __syncthreads();
    }
}

// ------------------------- skew hx/hy -------------------------
__global__ __launch_bounds__(256) void k_skew(const float* __restrict__ wx,
                                              const float* __restrict__ wy) {
    int b = blockIdx.x;
    int t = threadIdx.x;
    int h = t & 127, pr = t >> 7;
    __shared__ float sf[32 * NN];
    __shared__ float swx[128 * 33];
    __shared__ float swy[128 * 33];
    float ax[18], ay[18];
#pragma unroll
    for (int n = 0; n < 18; n++) { ax[n] = 0.f; ay[n] = 0.f; }
    const float* fb = g_feats + (size_t)b * MIDD * NN;

    for (int mc = 0; mc < MIDD; mc += 32) {
        int mlen = min(32, MIDD - mc);
        for (int i = t; i < mlen * NN; i += 256) sf[i] = fb[mc * NN + i];
        if (pr == 0) {
            for (int j = 0; j < mlen; j++) swx[h * 33 + j] = wx[(size_t)h * MIDD + mc + j];
        } else {
            for (int j = 0; j < mlen; j++) swy[h * 33 + j] = wy[(size_t)h * MIDD + mc + j];
        }
        __syncthreads();
        for (int j = 0; j < mlen; j++) {
            float wxv = swx[h * 33 + j], wyv = swy[h * 33 + j];
            const float* sr = sf + j * NN + pr * 18;
#pragma unroll
            for (int n = 0; n < 18; n++) {
                float fv = sr[n];
                ax[n] += wxv * fv;
                ay[n] += wyv * fv;
            }
        }
        __syncthreads();
    }
#pragma unroll
    for (int n = 0; n < 18; n++) {
        g_hx[(size_t)b * HIDD * NN + h * NN + pr * 18 + n] = ax[n];
        g_hy[(size_t)b * HIDD * NN + h * NN + pr * 18 + n] = ay[n];
    }
}

// ------------------------- assignment + permutation mix ---------------------
__global__ __launch_bounds__(512) void k_assign(const float* __restrict__ b1,
                                                const float* __restrict__ w2,
                                                const float* __restrict__ b2p,
                                                const float* __restrict__ lrp) {
    int b = blockIdx.x, t = threadIdx.x;
    __shared__ float outS[1296], CSh[1296], LG[1296], PS[1296], DS[1296];
    __shared__ float saS[36], w2S[128], b1S[128];
    if (t < 128) { w2S[t] = w2[t]; b1S[t] = b1[t]; }
    if (t < 36) saS[t] = g_sigatt[b * NN + t];
    __syncthreads();

    const float* hxb = g_hx + (size_t)b * HIDD * NN;
    const float* hyb = g_hy + (size_t)b * HIDD * NN;
    float b2v = b2p[0];

    for (int p = t; p < 1296; p += 512) {
        int i = p / 36, j = p - i * 36;
        float s = 0.f;
#pragma unroll 8
        for (int h = 0; h < HIDD; h++) {
            float v = hxb[h * NN + i] + hyb[h * NN + j] + b1S[h];
            s += w2S[h] * fmaxf(v, 0.f);
        }
        outS[p] = s + b2v;
    }
    __syncthreads();
    for (int p = t; p < 1296; p += 512) {
        int i = p / 36, j = p - i * 36;
        CSh[p] = outS[p] - outS[j * 36 + i];
        LG[p] = 0.f;
    }
    __syncthreads();

    float lrabs = fabsf(lrp[0]);
    for (int it = 0; it < 3; it++) {
        if (t < 36) {
            float mx = -1e30f;
            for (int j = 0; j < 36; j++) mx = fmaxf(mx, LG[t * 36 + j]);
            float sum = 0.f;
            for (int j = 0; j < 36; j++) {
                float e = expf(LG[t * 36 + j] - mx);
                PS[t * 36 + j] = e;
                sum += e;
            }
            float inv = 1.f / sum;
            for (int j = 0; j < 36; j++) PS[t * 36 + j] *= inv;
        }
        __syncthreads();
        if (t < 36) {
            int l = t;
            float tot = 0.f;
            for (int i = 0; i < 36; i++) tot += PS[i * 36 + l];
            float run = 0.f;
            for (int i = 0; i < 36; i++) {
                float p = PS[i * 36 + l];
                run += p;
                DS[i * 36 + l] = tot - 2.f * run + p;
            }
        }
        __syncthreads();
        for (int p = t; p < 1296; p += 512) {
            int i = p / 36, j = p - i * 36;
            float gsum = 0.f;
#pragma unroll
            for (int l = 0; l < 36; l++) gsum += DS[i * 36 + l] * CSh[j * 36 + l];
            LG[p] -= lrabs * gsum;
        }
        __syncthreads();
    }
    if (t < 36) {
        float mx = -1e30f;
        for (int j = 0; j < 36; j++) mx = fmaxf(mx, LG[t * 36 + j]);
        float sum = 0.f;
        for (int j = 0; j < 36; j++) {
            float e = expf(LG[t * 36 + j] - mx);
            PS[t * 36 + j] = e;
            sum += e;
        }
        float inv = 1.f / sum;
        for (int j = 0; j < 36; j++) PS[t * 36 + j] *= inv;
    }
    __syncthreads();

    // x_seq[i][b][c] = sum_l feats[b,c,l]*sig(att)[l]*A[i,l]  (fp32, padded)
    const float* fb = g_feats + (size_t)b * MIDD * NN;
    for (int p = t; p < MIDD * NN; p += 512) {
        int c = p / 36, i = p - c * 36;
        float s = 0.f;
#pragma unroll
        for (int l = 0; l < 36; l++) s += fb[c * 36 + l] * saS[l] * PS[i * 36 + l];
        g_xseq[((size_t)i * BB + b) * KP2 + c] = s;
    }
    for (int p = t; p < (KP2 - MIDD) * NN; p += 512) {
        int c = MIDD + p / 36, i = p % 36;
        g_xseq[((size_t)i * BB + b) * KP2 + c] = 0.f;
    }
}

// ------------------------- launch -------------------------
extern "C" void kernel_launch(void* const* d_in, const int* in_sizes, int n_in,
                              void* d_out, int out_size) {
    const float* boxes     = (const float*)d_in[0];
    const float* attention = (const float*)d_in[1];
    const float* features  = (const float*)d_in[2];
    const float* conv_w    = (const float*)d_in[3];
    const float* conv_b    = (const float*)d_in[4];
    const float* skew_wx   = (const float*)d_in[5];
    const float* skew_wy   = (const float*)d_in[6];
    const float* skew_b1   = (const float*)d_in[7];
    const float* skew_w2   = (const float*)d_in[8];
    const float* skew_b2   = (const float*)d_in[9];
    const float* w_ih      = (const float*)d_in[10];
    const float* w_hh      = (const float*)d_in[11];
    const float* b_ih      = (const float*)d_in[12];
    const float* b_hh      = (const float*)d_in[13];
    const float* lr        = (const float*)d_in[14];

    static int attr_done = 0;
    if (!attr_done) {
        cudaFuncSetAttribute(k_conv, cudaFuncAttributeMaxDynamicSharedMemorySize, F_DYN);
        cudaFuncSetAttribute(k_gin,  cudaFuncAttributeMaxDynamicSharedMemorySize, F_DYN);
        cudaFuncSetAttribute(k_lstm, cudaFuncAttributeMaxDynamicSharedMemorySize, H_DYN);
        attr_done = 1;
    }

    k_init<<<(BB * OUTD + 255) / 256, 256>>>();
    k_scale<<<1, 128>>>(boxes);
    k_head<<<(BB * NN + 255) / 256, 256>>>(boxes, attention);
    k_pad_wih<<<(G4 * KP2 + 511) / 512, 512>>>(w_ih);
    k_split_whh<<<(G4 * OUTD + 511) / 512, 512>>>(w_hh);

    k_conv<<<dim3(4, 72), 256, F_DYN>>>(conv_w, features, conv_b);
    k_skew<<<BB, 256>>>(skew_wx, skew_wy);
    k_assign<<<BB, 512>>>(skew_b1, skew_w2, skew_b2, lr);
    k_gin<<<dim3(36, 64), 256, F_DYN>>>(b_ih, b_hh);

    k_lstm<<<NBLK_LSTM, 256, H_DYN>>>((float*)d_out);
}

// round 5
// speedup vs baseline: 1.0720x; 1.0720x over previous
#include <cuda_runtime.h>
#include <cuda_bf16.h>
#include <mma.h>
#include <cstdint>

using namespace nvcuda;
typedef __nv_bfloat16 bf16;

#define BB   128
#define NN   36
#define FEATD 2048
#define MIDD 517
#define HIDD 128
#define OUTD 1024
#define G4   4096
#define KP2  576
#define TSTEPS 36

// ---- bf16x3 core geometry: 128x64 tile, 8 warps (4M x 2N), warp 32x32 ----
#define C_LD   40                        // smem row stride in bf16 elems (80B)
#define C_OAHI 0
#define C_OALO 10240
#define C_OBHI 20480
#define C_OBLO 25600
#define C_STG  30720
#define C_DYN  (3 * C_STG)               // 92160 bytes

// ------------------------- scratch -------------------------
__device__ float g_scale[BB];
__device__ float g_sigatt[BB * NN];
__device__ float g_feats[BB * MIDD * NN];                 // [b][m][n] fp32
__device__ float g_hx[BB * HIDD * NN];
__device__ float g_hy[BB * HIDD * NN];

__device__ __align__(16) bf16 g_feat_hi[(size_t)BB * NN * FEATD];
__device__ __align__(16) bf16 g_feat_lo[(size_t)BB * NN * FEATD];
__device__ __align__(16) bf16 g_convw_hi[512 * FEATD];
__device__ __align__(16) bf16 g_convw_lo[512 * FEATD];
__device__ __align__(16) bf16 g_wih_hi[(size_t)G4 * KP2];   // col = u*4+g
__device__ __align__(16) bf16 g_wih_lo[(size_t)G4 * KP2];
__device__ __align__(16) bf16 g_whh_hi[(size_t)G4 * OUTD];  // reordered rows
__device__ __align__(16) bf16 g_whh_lo[(size_t)G4 * OUTD];
__device__ __align__(16) bf16 g_xh[(size_t)TSTEPS * BB * KP2];  // [t*128+b][k]
__device__ __align__(16) bf16 g_xl[(size_t)TSTEPS * BB * KP2];
__device__ float g_gates_in[(size_t)TSTEPS * BB * G4];      // reordered cols
__device__ __align__(16) bf16 g_hhi0[BB * OUTD];
__device__ __align__(16) bf16 g_hlo0[BB * OUTD];
__device__ __align__(16) bf16 g_hhi1[BB * OUTD];
__device__ __align__(16) bf16 g_hlo1[BB * OUTD];
__device__ float g_c[BB * OUTD];
__device__ __align__(16) float g_part[2][BB][G4];           // split-K partials
__device__ unsigned g_scnt[64];                              // per-ntile tickets

// ------------------------- helpers -------------------------
__device__ __forceinline__ void split_write(float v, bf16* hi, bf16* lo) {
    bf16 h = __float2bfloat16(v);
    *hi = h;
    *lo = __float2bfloat16(v - __bfloat162float(h));
}

__device__ __forceinline__ void cp16(void* dst, const void* src) {
    unsigned d = (unsigned)__cvta_generic_to_shared(dst);
    asm volatile("cp.async.ca.shared.global [%0], [%1], 16;\n" ::"r"(d), "l"(src));
}

// ------------------------- prep kernels -------------------------
__global__ void k_init() {
    int idx = blockIdx.x * blockDim.x + threadIdx.x;
    if (idx < 64) g_scnt[idx] = 0;
    if (idx >= BB * OUTD) return;
    g_hhi0[idx] = __float2bfloat16(0.f);
    g_hlo0[idx] = __float2bfloat16(0.f);
    g_c[idx] = 0.f;
}

__global__ void k_scale(const float* __restrict__ boxes) {
    int b = blockIdx.x * blockDim.x + threadIdx.x;
    if (b >= BB) return;
    const float* p = boxes + (size_t)b * 4 * NN;
    float m = -1e30f;
    for (int i = 0; i < 4 * NN; i++) m = fmaxf(m, p[i]);
    g_scale[b] = m;
}

__global__ void k_head(const float* __restrict__ boxes,
                       const float* __restrict__ att) {
    int idx = blockIdx.x * blockDim.x + threadIdx.x;
    if (idx >= BB * NN) return;
    int b = idx / NN, n = idx - b * NN;
    float inv = 1.f / g_scale[b];
    for (int r = 0; r < 4; r++)
        g_feats[(size_t)b * MIDD * NN + r * NN + n] =
            boxes[(size_t)b * 4 * NN + r * NN + n] * inv;
    float a = att[idx];
    g_feats[(size_t)b * MIDD * NN + 4 * NN + n] = a;
    g_sigatt[idx] = 1.f / (1.f + expf(-a));
}

__global__ void k_split_feat(const float* __restrict__ src) {
    size_t idx = (size_t)blockIdx.x * blockDim.x + threadIdx.x;
    if (idx >= (size_t)BB * NN * FEATD) return;
    split_write(src[idx], &g_feat_hi[idx], &g_feat_lo[idx]);
}

__global__ void k_split_convw(const float* __restrict__ src) {
    size_t idx = (size_t)blockIdx.x * blockDim.x + threadIdx.x;
    if (idx >= (size_t)512 * FEATD) return;
    split_write(src[idx], &g_convw_hi[idx], &g_convw_lo[idx]);
}

__global__ void k_split_wih(const float* __restrict__ wih) {
    size_t idx = (size_t)blockIdx.x * blockDim.x + threadIdx.x;
    if (idx >= (size_t)G4 * KP2) return;
    int cr = (int)(idx / KP2), k = (int)(idx - (size_t)cr * KP2);
    int u = cr >> 2, g = cr & 3;
    float v = (k < MIDD) ? wih[(size_t)(g * OUTD + u) * MIDD + k] : 0.f;
    split_write(v, &g_wih_hi[idx], &g_wih_lo[idx]);
}

__global__ void k_split_whh(const float* __restrict__ whh) {
    size_t idx = (size_t)blockIdx.x * blockDim.x + threadIdx.x;
    if (idx >= (size_t)G4 * OUTD) return;
    int cr = (int)(idx / OUTD), k = (int)(idx - (size_t)cr * OUTD);
    int u = cr >> 2, g = cr & 3;
    float v = whh[(size_t)(g * OUTD + u) * OUTD + k];
    split_write(v, &g_whh_hi[idx], &g_whh_lo[idx]);
}

// ------------------------- bf16x3 core: 128x64, 256 thr ---------------------
// C = A[m0:+128, kbeg:kbeg+32*nch] * B[n0:+64, same-k]^T   (both K-contiguous)
__device__ __forceinline__ float* gemm_core(
    const bf16* __restrict__ Ahi, const bf16* __restrict__ Alo,
    const bf16* __restrict__ Bhi, const bf16* __restrict__ Blo,
    int lda, int ldb, int nch, int m0, int n0, int kbeg, char* sm)
{
    const int t = threadIdx.x, w = t >> 5;
    const int wm = w >> 1, wn = w & 1;       // 4 x 2 warp grid

    wmma::fragment<wmma::accumulator, 16, 16, 16, float> acc[2][2];
#pragma unroll
    for (int i = 0; i < 2; i++)
#pragma unroll
        for (int j = 0; j < 2; j++) wmma::fill_fragment(acc[i][j], 0.f);

    auto issue = [&](int jc) {
        char* st = sm + (jc % 3) * C_STG;
        int k0 = kbeg + jc * 32;
#pragma unroll
        for (int u = 0; u < 6; u++) {
            int seg = t + u * 256;
            const bf16* src;
            char* dst;
            if (seg < 512) {
                int row = seg >> 2, s = seg & 3;
                src = Ahi + (size_t)(m0 + row) * lda + k0 + s * 8;
                dst = st + C_OAHI + row * 80 + s * 16;
            } else if (seg < 1024) {
                int x = seg - 512;
                int row = x >> 2, s = x & 3;
                src = Alo + (size_t)(m0 + row) * lda + k0 + s * 8;
                dst = st + C_OALO + row * 80 + s * 16;
            } else if (seg < 1280) {
                int x = seg - 1024;
                int row = x >> 2, s = x & 3;
                src = Bhi + (size_t)(n0 + row) * ldb + k0 + s * 8;
                dst = st + C_OBHI + row * 80 + s * 16;
            } else {
                int x = seg - 1280;
                int row = x >> 2, s = x & 3;
                src = Blo + (size_t)(n0 + row) * ldb + k0 + s * 8;
                dst = st + C_OBLO + row * 80 + s * 16;
            }
            cp16(dst, src);
        }
        asm volatile("cp.async.commit_group;\n" ::: "memory");
    };

    issue(0);
    issue(1);
    for (int i = 0; i < nch; i++) {
        if (i < nch - 1)
            asm volatile("cp.async.wait_group 1;\n" ::: "memory");
        else
            asm volatile("cp.async.wait_group 0;\n" ::: "memory");
        __syncthreads();
        if (i + 2 < nch) issue(i + 2);

        char* st = sm + (i % 3) * C_STG;
        bf16* sAhi = (bf16*)(st + C_OAHI);
        bf16* sAlo = (bf16*)(st + C_OALO);
        bf16* sBhi = (bf16*)(st + C_OBHI);
        bf16* sBlo = (bf16*)(st + C_OBLO);
#pragma unroll
        for (int ks = 0; ks < 2; ks++) {
            const int kk = ks * 16;
            wmma::fragment<wmma::matrix_a, 16, 16, 16, bf16, wmma::row_major> ah[2], al[2];
            wmma::fragment<wmma::matrix_b, 16, 16, 16, bf16, wmma::col_major> bh[2], bl[2];
#pragma unroll
            for (int i2 = 0; i2 < 2; i2++) {
                wmma::load_matrix_sync(ah[i2], &sAhi[(wm * 32 + i2 * 16) * C_LD + kk], C_LD);
                wmma::load_matrix_sync(al[i2], &sAlo[(wm * 32 + i2 * 16) * C_LD + kk], C_LD);
                wmma::load_matrix_sync(bh[i2], &sBhi[(wn * 32 + i2 * 16) * C_LD + kk], C_LD);
                wmma::load_matrix_sync(bl[i2], &sBlo[(wn * 32 + i2 * 16) * C_LD + kk], C_LD);
            }
#pragma unroll
            for (int i2 = 0; i2 < 2; i2++)
#pragma unroll
                for (int j2 = 0; j2 < 2; j2++)
                    wmma::mma_sync(acc[i2][j2], ah[i2], bh[j2], acc[i2][j2]);
#pragma unroll
            for (int i2 = 0; i2 < 2; i2++)
#pragma unroll
                for (int j2 = 0; j2 < 2; j2++)
                    wmma::mma_sync(acc[i2][j2], ah[i2], bl[j2], acc[i2][j2]);
#pragma unroll
            for (int i2 = 0; i2 < 2; i2++)
#pragma unroll
                for (int j2 = 0; j2 < 2; j2++)
                    wmma::mma_sync(acc[i2][j2], al[i2], bh[j2], acc[i2][j2]);
        }
    }
    __syncthreads();
    float* Cs = (float*)sm;   // 32KB, aliases consumed stages
#pragma unroll
    for (int i2 = 0; i2 < 2; i2++)
#pragma unroll
        for (int j2 = 0; j2 < 2; j2++)
            wmma::store_matrix_sync(&Cs[(wm * 32 + i2 * 16) * 64 + wn * 32 + j2 * 16],
                                    acc[i2][j2], 64, wmma::mem_row_major);
    __syncthreads();
    return Cs;
}

// ------------------------- conv GEMM -------------------------
__global__ __launch_bounds__(256) void k_conv(const float* __restrict__ convb) {
    extern __shared__ char sm[];
    int m0 = blockIdx.x * 128, n0 = blockIdx.y * 64;
    float* Cs = gemm_core(g_convw_hi, g_convw_lo, g_feat_hi, g_feat_lo,
                          FEATD, FEATD, FEATD / 32, m0, n0, 0, sm);
    for (int idx = threadIdx.x; idx < 128 * 64; idx += 256) {
        int r = idx >> 6, cc = idx & 63;
        int m = m0 + r, col = n0 + cc;
        int b = col / NN, n = col - b * NN;
        g_feats[(size_t)b * MIDD * NN + (5 + m) * NN + n] = Cs[idx] + convb[m];
    }
}

// ------------------------- input-gate GEMM -------------------------
__global__ __launch_bounds__(256) void k_gin(const float* __restrict__ bih,
                                             const float* __restrict__ bhh) {
    extern __shared__ char sm[];
    int m0 = blockIdx.x * 128, n0 = blockIdx.y * 64;
    float* Cs = gemm_core(g_xh, g_xl, g_wih_hi, g_wih_lo,
                          KP2, KP2, KP2 / 32, m0, n0, 0, sm);
    for (int idx = threadIdx.x; idx < 128 * 64; idx += 256) {
        int r = idx >> 6, cc = idx & 63;
        int row = m0 + r, col = n0 + cc;
        int orig = (col & 3) * OUTD + (col >> 2);
        g_gates_in[(size_t)row * G4 + col] = Cs[idx] + bih[orig] + bhh[orig];
    }
}

// ------------------------- recurrent step: split-K2 + fused update ----------
__global__ __launch_bounds__(256) void k_step(int s, float* __restrict__ outc) {
    extern __shared__ char sm[];
    const int kz = blockIdx.x;          // 0/1: K half
    const int ntile = blockIdx.y;       // 64 tiles of N=64
    const int n0 = ntile * 64;
    const int t = threadIdx.x;

    const bf16* hin_hi = (s & 1) ? g_hhi1 : g_hhi0;
    const bf16* hin_lo = (s & 1) ? g_hlo1 : g_hlo0;
    bf16* hout_hi = (s & 1) ? g_hhi0 : g_hhi1;
    bf16* hout_lo = (s & 1) ? g_hlo0 : g_hlo1;

    float* Cs = gemm_core(hin_hi, hin_lo, g_whh_hi, g_whh_lo,
                          OUTD, OUTD, 16, 0, n0, kz * 512, sm);

    // publish this half's partial
    float4* dst4 = (float4*)&g_part[kz][0][n0];
    const float4* Cs4 = (const float4*)Cs;
    for (int p = t; p < 2048; p += 256)
        dst4[(p >> 4) * (G4 / 4) + (p & 15)] = Cs4[p];
    __threadfence();

    __shared__ unsigned s_last;
    if (t == 0) s_last = (atomicAdd(&g_scnt[ntile], 1u) == 1u);
    __syncthreads();
    if (!s_last) return;
    __threadfence();  // acquire: see peer's partial

    const int oz = kz ^ 1;
    const float* gin = g_gates_in + (size_t)s * BB * G4;
    for (int p = t; p < 2048; p += 256) {
        int b = p >> 4, lu = p & 15;
        float4 mine = Cs4[p];
        float4 oth = *(const float4*)&g_part[oz][b][n0 + lu * 4];
        float4 gv = *(const float4*)(gin + (size_t)b * G4 + n0 + lu * 4);
        float ig = mine.x + oth.x + gv.x;
        float fg = mine.y + oth.y + gv.y;
        float gg = mine.z + oth.z + gv.z;
        float og = mine.w + oth.w + gv.w;
        float si = 1.f / (1.f + expf(-ig));
        float sf = 1.f / (1.f + expf(-fg));
        float so = 1.f / (1.f + expf(-og));
        int u = (n0 >> 2) + lu;
        int ci = b * OUTD + u;
        float c = sf * g_c[ci] + si * tanhf(gg);
        g_c[ci] = c;
        float h = so * tanhf(c);
        split_write(h, &hout_hi[ci], &hout_lo[ci]);
        if (outc) outc[ci] = c;
    }
    if (t == 0) g_scnt[ntile] = 0;   // re-arm for next step's launch
}

// ------------------------- skew hx/hy -------------------------
__global__ __launch_bounds__(256) void k_skew(const float* __restrict__ wx,
                                              const float* __restrict__ wy) {
    int b = blockIdx.x;
    int t = threadIdx.x;
    int h = t & 127, pr = t >> 7;
    __shared__ float sf[32 * NN];
    __shared__ float swx[128 * 33];
    __shared__ float swy[128 * 33];
    float ax[18], ay[18];
#pragma unroll
    for (int n = 0; n < 18; n++) { ax[n] = 0.f; ay[n] = 0.f; }
    const float* fb = g_feats + (size_t)b * MIDD * NN;

    for (int mc = 0; mc < MIDD; mc += 32) {
        int mlen = min(32, MIDD - mc);
        for (int i = t; i < mlen * NN; i += 256) sf[i] = fb[mc * NN + i];
        if (pr == 0) {
            for (int j = 0; j < mlen; j++) swx[h * 33 + j] = wx[(size_t)h * MIDD + mc + j];
        } else {
            for (int j = 0; j < mlen; j++) swy[h * 33 + j] = wy[(size_t)h * MIDD + mc + j];
        }
        __syncthreads();
        for (int j = 0; j < mlen; j++) {
            float wxv = swx[h * 33 + j], wyv = swy[h * 33 + j];
            const float* sr = sf + j * NN + pr * 18;
#pragma unroll
            for (int n = 0; n < 18; n++) {
                float fv = sr[n];
                ax[n] += wxv * fv;
                ay[n] += wyv * fv;
            }
        }
        __syncthreads();
    }
#pragma unroll
    for (int n = 0; n < 18; n++) {
        g_hx[(size_t)b * HIDD * NN + h * NN + pr * 18 + n] = ax[n];
        g_hy[(size_t)b * HIDD * NN + h * NN + pr * 18 + n] = ay[n];
    }
}

// ------------------------- assignment + permutation mix ---------------------
__global__ __launch_bounds__(512) void k_assign(const float* __restrict__ b1,
                                                const float* __restrict__ w2,
                                                const float* __restrict__ b2p,
                                                const float* __restrict__ lrp) {
    int b = blockIdx.x, t = threadIdx.x;
    __shared__ float outS[1296], CSh[1296], LG[1296], PS[1296], DS[1296];
    __shared__ float saS[36], w2S[128], b1S[128];
    if (t < 128) { w2S[t] = w2[t]; b1S[t] = b1[t]; }
    if (t < 36) saS[t] = g_sigatt[b * NN + t];
    __syncthreads();

    const float* hxb = g_hx + (size_t)b * HIDD * NN;
    const float* hyb = g_hy + (size_t)b * HIDD * NN;
    float b2v = b2p[0];

    for (int p = t; p < 1296; p += 512) {
        int i = p / 36, j = p - i * 36;
        float s = 0.f;
#pragma unroll 8
        for (int h = 0; h < HIDD; h++) {
            float v = hxb[h * NN + i] + hyb[h * NN + j] + b1S[h];
            s += w2S[h] * fmaxf(v, 0.f);
        }
        outS[p] = s + b2v;
    }
    __syncthreads();
    for (int p = t; p < 1296; p += 512) {
        int i = p / 36, j = p - i * 36;
        CSh[p] = outS[p] - outS[j * 36 + i];
        LG[p] = 0.f;
    }
    __syncthreads();

    float lrabs = fabsf(lrp[0]);
    for (int it = 0; it < 3; it++) {
        if (t < 36) {
            float mx = -1e30f;
            for (int j = 0; j < 36; j++) mx = fmaxf(mx, LG[t * 36 + j]);
            float sum = 0.f;
            for (int j = 0; j < 36; j++) {
                float e = expf(LG[t * 36 + j] - mx);
                PS[t * 36 + j] = e;
                sum += e;
            }
            float inv = 1.f / sum;
            for (int j = 0; j < 36; j++) PS[t * 36 + j] *= inv;
        }
        __syncthreads();
        if (t < 36) {
            int l = t;
            float tot = 0.f;
            for (int i = 0; i < 36; i++) tot += PS[i * 36 + l];
            float run = 0.f;
            for (int i = 0; i < 36; i++) {
                float p = PS[i * 36 + l];
                run += p;
                DS[i * 36 + l] = tot - 2.f * run + p;
            }
        }
        __syncthreads();
        for (int p = t; p < 1296; p += 512) {
            int i = p / 36, j = p - i * 36;
            float gsum = 0.f;
#pragma unroll
            for (int l = 0; l < 36; l++) gsum += DS[i * 36 + l] * CSh[j * 36 + l];
            LG[p] -= lrabs * gsum;
        }
        __syncthreads();
    }
    if (t < 36) {
        float mx = -1e30f;
        for (int j = 0; j < 36; j++) mx = fmaxf(mx, LG[t * 36 + j]);
        float sum = 0.f;
        for (int j = 0; j < 36; j++) {
            float e = expf(LG[t * 36 + j] - mx);
            PS[t * 36 + j] = e;
            sum += e;
        }
        float inv = 1.f / sum;
        for (int j = 0; j < 36; j++) PS[t * 36 + j] *= inv;
    }
    __syncthreads();

    // x_seq[i][b][c] = sum_l feats[b,c,l]*sig(att)[l]*A[i,l] -> bf16 split
    const float* fb = g_feats + (size_t)b * MIDD * NN;
    for (int p = t; p < MIDD * NN; p += 512) {
        int c = p / 36, i = p - c * 36;
        float s = 0.f;
#pragma unroll
        for (int l = 0; l < 36; l++) s += fb[c * 36 + l] * saS[l] * PS[i * 36 + l];
        size_t di = ((size_t)i * BB + b) * KP2 + c;
        split_write(s, &g_xh[di], &g_xl[di]);
    }
    for (int p = t; p < (KP2 - MIDD) * NN; p += 512) {
        int c = MIDD + p / 36, i = p % 36;
        size_t di = ((size_t)i * BB + b) * KP2 + c;
        g_xh[di] = __float2bfloat16(0.f);
        g_xl[di] = __float2bfloat16(0.f);
    }
}

// ------------------------- launch -------------------------
extern "C" void kernel_launch(void* const* d_in, const int* in_sizes, int n_in,
                              void* d_out, int out_size) {
    const float* boxes     = (const float*)d_in[0];
    const float* attention = (const float*)d_in[1];
    const float* features  = (const float*)d_in[2];
    const float* conv_w    = (const float*)d_in[3];
    const float* conv_b    = (const float*)d_in[4];
    const float* skew_wx   = (const float*)d_in[5];
    const float* skew_wy   = (const float*)d_in[6];
    const float* skew_b1   = (const float*)d_in[7];
    const float* skew_w2   = (const float*)d_in[8];
    const float* skew_b2   = (const float*)d_in[9];
    const float* w_ih      = (const float*)d_in[10];
    const float* w_hh      = (const float*)d_in[11];
    const float* b_ih      = (const float*)d_in[12];
    const float* b_hh      = (const float*)d_in[13];
    const float* lr        = (const float*)d_in[14];

    static int attr_done = 0;
    if (!attr_done) {
        cudaFuncSetAttribute(k_conv, cudaFuncAttributeMaxDynamicSharedMemorySize, C_DYN);
        cudaFuncSetAttribute(k_gin,  cudaFuncAttributeMaxDynamicSharedMemorySize, C_DYN);
        cudaFuncSetAttribute(k_step, cudaFuncAttributeMaxDynamicSharedMemorySize, C_DYN);
        attr_done = 1;
    }

    k_init<<<(BB * OUTD + 255) / 256, 256>>>();
    k_scale<<<1, 128>>>(boxes);
    k_head<<<(BB * NN + 255) / 256, 256>>>(boxes, attention);
    {
        size_t n = (size_t)BB * NN * FEATD;
        k_split_feat<<<(unsigned)((n + 511) / 512), 512>>>(features);
    }
    k_split_convw<<<(512 * FEATD + 511) / 512, 512>>>(conv_w);
    k_split_wih<<<(G4 * KP2 + 511) / 512, 512>>>(w_ih);
    k_split_whh<<<(G4 * OUTD + 511) / 512, 512>>>(w_hh);

    k_conv<<<dim3(4, 72), 256, C_DYN>>>(conv_b);
    k_skew<<<BB, 256>>>(skew_wx, skew_wy);
    k_assign<<<BB, 512>>>(skew_b1, skew_w2, skew_b2, lr);
    k_gin<<<dim3(36, 64), 256, C_DYN>>>(b_ih, b_hh);

    for (int s = 0; s < TSTEPS; s++) {
        k_step<<<dim3(2, 64), 256, C_DYN>>>(s, s == TSTEPS - 1 ? (float*)d_out : nullptr);
    }
}

// round 6
// speedup vs baseline: 1.5898x; 1.4831x over previous
#include <cuda_runtime.h>
#include <cuda_fp16.h>
#include <mma.h>
#include <cstdint>

using namespace nvcuda;
typedef __half h16;

#define BB   128
#define NN   36
#define FEATD 2048
#define MIDD 517
#define HIDD 128
#define OUTD 1024
#define G4   4096
#define KP2  576
#define TSTEPS 36

// ---- fp16 core geometry: 128x64 tile, 8 warps (4M x 2N), k-chunk 32 ----
#define C_LD  40                         // smem row stride in fp16 elems (80B)
#define C_OA  0                          // A hi : 128*80 = 10240
#define C_OBH 10240                      // B hi : 64*80 = 5120
#define C_OBL 15360                      // B lo : 5120
#define C_STG 20480
#define C_DYN (3 * C_STG)                // 61440 bytes

// ------------------------- scratch -------------------------
__device__ float g_scale[BB];
__device__ float g_sigatt[BB * NN];
__device__ float g_feats[BB * MIDD * NN];                 // [b][m][n] fp32
__device__ float g_hx[BB * HIDD * NN];
__device__ float g_hy[BB * HIDD * NN];

__device__ __align__(16) h16 g_feat_hi[(size_t)BB * NN * FEATD];
__device__ __align__(16) h16 g_feat_lo[(size_t)BB * NN * FEATD];
__device__ __align__(16) h16 g_convw_h[512 * FEATD];        // A of conv: hi only
__device__ __align__(16) h16 g_wih_hi[(size_t)G4 * KP2];    // col = u*4+g
__device__ __align__(16) h16 g_wih_lo[(size_t)G4 * KP2];
__device__ __align__(16) h16 g_whh_h[(size_t)G4 * OUTD];    // reordered, hi only
__device__ __align__(16) h16 g_xh[(size_t)TSTEPS * BB * KP2];   // A of gin: hi
__device__ float g_gates_in[(size_t)TSTEPS * BB * G4];      // reordered cols
__device__ __align__(16) h16 g_h0[BB * OUTD];
__device__ __align__(16) h16 g_h1[BB * OUTD];
__device__ float g_c[BB * OUTD];
__device__ __align__(16) float g_part[2][BB][G4];           // split-K partials
__device__ unsigned g_scnt[64];                              // per-ntile tickets

// ------------------------- helpers -------------------------
__device__ __forceinline__ void split_write(float v, h16* hi, h16* lo) {
    h16 h = __float2half(v);
    *hi = h;
    *lo = __float2half(v - __half2float(h));
}

__device__ __forceinline__ void cp16(void* dst, const void* src) {
    unsigned d = (unsigned)__cvta_generic_to_shared(dst);
    asm volatile("cp.async.ca.shared.global [%0], [%1], 16;\n" ::"r"(d), "l"(src));
}

// ------------------------- prep kernels -------------------------
__global__ void k_init() {
    int idx = blockIdx.x * blockDim.x + threadIdx.x;
    if (idx < 64) g_scnt[idx] = 0;
    if (idx >= BB * OUTD) return;
    g_h0[idx] = __float2half(0.f);
    g_c[idx] = 0.f;
}

__global__ void k_scale(const float* __restrict__ boxes) {
    int b = blockIdx.x * blockDim.x + threadIdx.x;
    if (b >= BB) return;
    const float* p = boxes + (size_t)b * 4 * NN;
    float m = -1e30f;
    for (int i = 0; i < 4 * NN; i++) m = fmaxf(m, p[i]);
    g_scale[b] = m;
}

__global__ void k_head(const float* __restrict__ boxes,
                       const float* __restrict__ att) {
    int idx = blockIdx.x * blockDim.x + threadIdx.x;
    if (idx >= BB * NN) return;
    int b = idx / NN, n = idx - b * NN;
    float inv = 1.f / g_scale[b];
    for (int r = 0; r < 4; r++)
        g_feats[(size_t)b * MIDD * NN + r * NN + n] =
            boxes[(size_t)b * 4 * NN + r * NN + n] * inv;
    float a = att[idx];
    g_feats[(size_t)b * MIDD * NN + 4 * NN + n] = a;
    g_sigatt[idx] = 1.f / (1.f + expf(-a));
}

__global__ void k_split_feat(const float* __restrict__ src) {
    size_t idx = (size_t)blockIdx.x * blockDim.x + threadIdx.x;
    if (idx >= (size_t)BB * NN * FEATD) return;
    split_write(src[idx], &g_feat_hi[idx], &g_feat_lo[idx]);
}

__global__ void k_cw(const float* __restrict__ src) {
    size_t idx = (size_t)blockIdx.x * blockDim.x + threadIdx.x;
    if (idx >= (size_t)512 * FEATD) return;
    g_convw_h[idx] = __float2half(src[idx]);
}

__global__ void k_split_wih(const float* __restrict__ wih) {
    size_t idx = (size_t)blockIdx.x * blockDim.x + threadIdx.x;
    if (idx >= (size_t)G4 * KP2) return;
    int cr = (int)(idx / KP2), k = (int)(idx - (size_t)cr * KP2);
    int u = cr >> 2, g = cr & 3;
    float v = (k < MIDD) ? wih[(size_t)(g * OUTD + u) * MIDD + k] : 0.f;
    split_write(v, &g_wih_hi[idx], &g_wih_lo[idx]);
}

__global__ void k_whh(const float* __restrict__ whh) {
    size_t idx = (size_t)blockIdx.x * blockDim.x + threadIdx.x;
    if (idx >= (size_t)G4 * OUTD) return;
    int cr = (int)(idx / OUTD), k = (int)(idx - (size_t)cr * OUTD);
    int u = cr >> 2, g = cr & 3;
    g_whh_h[idx] = __float2half(whh[(size_t)(g * OUTD + u) * OUTD + k]);
}

// ------------------------- fp16 GEMM core: 128x64 tile, 256 thr -------------
// NT=2: C = Ah[m0:+128,k] * (Bh+Bl)[n0:+64,k]^T ; NT=1: C = Ah * Bh^T
template <int NT>
__device__ __forceinline__ float* gemm_core(
    const h16* __restrict__ Ah,
    const h16* __restrict__ Bh, const h16* __restrict__ Bl,
    int lda, int ldb, int nch, int m0, int n0, int kbeg, char* sm)
{
    const int t = threadIdx.x, w = t >> 5;
    const int wm = w >> 1, wn = w & 1;       // 4 x 2 warp grid

    wmma::fragment<wmma::accumulator, 16, 16, 16, float> acc[2][2];
#pragma unroll
    for (int i = 0; i < 2; i++)
#pragma unroll
        for (int j = 0; j < 2; j++) wmma::fill_fragment(acc[i][j], 0.f);

    auto issue = [&](int jc) {
        char* st = sm + (jc % 3) * C_STG;
        int k0 = kbeg + jc * 32;
        const int NSEG = (NT == 2) ? 4 : 3;
#pragma unroll
        for (int u = 0; u < NSEG; u++) {
            int seg = t + u * 256;
            const h16* src;
            char* dst;
            if (seg < 512) {
                int row = seg >> 2, s = seg & 3;
                src = Ah + (size_t)(m0 + row) * lda + k0 + s * 8;
                dst = st + C_OA + row * 80 + s * 16;
            } else if (seg < 768) {
                int x = seg - 512;
                int row = x >> 2, s = x & 3;
                src = Bh + (size_t)(n0 + row) * ldb + k0 + s * 8;
                dst = st + C_OBH + row * 80 + s * 16;
            } else {
                int x = seg - 768;
                int row = x >> 2, s = x & 3;
                src = Bl + (size_t)(n0 + row) * ldb + k0 + s * 8;
                dst = st + C_OBL + row * 80 + s * 16;
            }
            cp16(dst, src);
        }
        asm volatile("cp.async.commit_group;\n" ::: "memory");
    };

    issue(0);
    issue(1);
    for (int i = 0; i < nch; i++) {
        if (i < nch - 1)
            asm volatile("cp.async.wait_group 1;\n" ::: "memory");
        else
            asm volatile("cp.async.wait_group 0;\n" ::: "memory");
        __syncthreads();
        if (i + 2 < nch) issue(i + 2);

        char* st = sm + (i % 3) * C_STG;
        h16* sA = (h16*)(st + C_OA);
        h16* sBh = (h16*)(st + C_OBH);
        h16* sBl = (h16*)(st + C_OBL);
#pragma unroll
        for (int ks = 0; ks < 2; ks++) {
            const int kk = ks * 16;
            wmma::fragment<wmma::matrix_a, 16, 16, 16, h16, wmma::row_major> a[2];
            wmma::fragment<wmma::matrix_b, 16, 16, 16, h16, wmma::col_major> bh[2];
#pragma unroll
            for (int i2 = 0; i2 < 2; i2++) {
                wmma::load_matrix_sync(a[i2], &sA[(wm * 32 + i2 * 16) * C_LD + kk], C_LD);
                wmma::load_matrix_sync(bh[i2], &sBh[(wn * 32 + i2 * 16) * C_LD + kk], C_LD);
            }
#pragma unroll
            for (int i2 = 0; i2 < 2; i2++)
#pragma unroll
                for (int j2 = 0; j2 < 2; j2++)
                    wmma::mma_sync(acc[i2][j2], a[i2], bh[j2], acc[i2][j2]);
            if (NT == 2) {
                wmma::fragment<wmma::matrix_b, 16, 16, 16, h16, wmma::col_major> bl[2];
#pragma unroll
                for (int i2 = 0; i2 < 2; i2++)
                    wmma::load_matrix_sync(bl[i2], &sBl[(wn * 32 + i2 * 16) * C_LD + kk], C_LD);
#pragma unroll
                for (int i2 = 0; i2 < 2; i2++)
#pragma unroll
                    for (int j2 = 0; j2 < 2; j2++)
                        wmma::mma_sync(acc[i2][j2], a[i2], bl[j2], acc[i2][j2]);
            }
        }
    }
    __syncthreads();
    float* Cs = (float*)sm;   // 32KB, aliases consumed stages
#pragma unroll
    for (int i2 = 0; i2 < 2; i2++)
#pragma unroll
        for (int j2 = 0; j2 < 2; j2++)
            wmma::store_matrix_sync(&Cs[(wm * 32 + i2 * 16) * 64 + wn * 32 + j2 * 16],
                                    acc[i2][j2], 64, wmma::mem_row_major);
    __syncthreads();
    return Cs;
}

// ------------------------- conv GEMM -------------------------
__global__ __launch_bounds__(256) void k_conv(const float* __restrict__ convb) {
    extern __shared__ char sm[];
    int m0 = blockIdx.x * 128, n0 = blockIdx.y * 64;
    float* Cs = gemm_core<2>(g_convw_h, g_feat_hi, g_feat_lo,
                             FEATD, FEATD, FEATD / 32, m0, n0, 0, sm);
    for (int idx = threadIdx.x; idx < 128 * 64; idx += 256) {
        int r = idx >> 6, cc = idx & 63;
        int m = m0 + r, col = n0 + cc;
        int b = col / NN, n = col - b * NN;
        g_feats[(size_t)b * MIDD * NN + (5 + m) * NN + n] = Cs[idx] + convb[m];
    }
}

// ------------------------- input-gate GEMM -------------------------
__global__ __launch_bounds__(256) void k_gin(const float* __restrict__ bih,
                                             const float* __restrict__ bhh) {
    extern __shared__ char sm[];
    int m0 = blockIdx.x * 128, n0 = blockIdx.y * 64;
    float* Cs = gemm_core<2>(g_xh, g_wih_hi, g_wih_lo,
                             KP2, KP2, KP2 / 32, m0, n0, 0, sm);
    for (int idx = threadIdx.x; idx < 128 * 64; idx += 256) {
        int r = idx >> 6, cc = idx & 63;
        int row = m0 + r, col = n0 + cc;
        int orig = (col & 3) * OUTD + (col >> 2);
        g_gates_in[(size_t)row * G4 + col] = Cs[idx] + bih[orig] + bhh[orig];
    }
}

// ------------------------- recurrent step: split-K2 + fused update ----------
__global__ __launch_bounds__(256) void k_step(int s, float* __restrict__ outc) {
    extern __shared__ char sm[];
    const int kz = blockIdx.x;          // 0/1: K half
    const int ntile = blockIdx.y;       // 64 tiles of N=64
    const int n0 = ntile * 64;
    const int t = threadIdx.x;

    const h16* hin = (s & 1) ? g_h1 : g_h0;
    h16* hout = (s & 1) ? g_h0 : g_h1;

    float* Cs = gemm_core<1>(hin, g_whh_h, g_whh_h,
                             OUTD, OUTD, 16, 0, n0, kz * 512, sm);

    // publish this half's partial
    float4* dst4 = (float4*)&g_part[kz][0][n0];
    const float4* Cs4 = (const float4*)Cs;
    for (int p = t; p < 2048; p += 256)
        dst4[(p >> 4) * (G4 / 4) + (p & 15)] = Cs4[p];
    __threadfence();

    __shared__ unsigned s_last;
    if (t == 0) s_last = (atomicAdd(&g_scnt[ntile], 1u) == 1u);
    __syncthreads();
    if (!s_last) return;
    __threadfence();  // acquire: see peer's partial

    const int oz = kz ^ 1;
    const float* gin = g_gates_in + (size_t)s * BB * G4;
    for (int p = t; p < 2048; p += 256) {
        int b = p >> 4, lu = p & 15;
        float4 mine = Cs4[p];
        float4 oth = *(const float4*)&g_part[oz][b][n0 + lu * 4];
        float4 gv = *(const float4*)(gin + (size_t)b * G4 + n0 + lu * 4);
        float ig = mine.x + oth.x + gv.x;
        float fg = mine.y + oth.y + gv.y;
        float gg = mine.z + oth.z + gv.z;
        float og = mine.w + oth.w + gv.w;
        float si = 1.f / (1.f + expf(-ig));
        float sf = 1.f / (1.f + expf(-fg));
        float so = 1.f / (1.f + expf(-og));
        int u = (n0 >> 2) + lu;
        int ci = b * OUTD + u;
        float c = sf * g_c[ci] + si * tanhf(gg);
        g_c[ci] = c;
        hout[ci] = __float2half(so * tanhf(c));
        if (outc) outc[ci] = c;
    }
    if (t == 0) g_scnt[ntile] = 0;   // re-arm for next step's launch
}

// ------------------------- skew hx/hy -------------------------
__global__ __launch_bounds__(256) void k_skew(const float* __restrict__ wx,
                                              const float* __restrict__ wy) {
    int b = blockIdx.x;
    int t = threadIdx.x;
    int h = t & 127, pr = t >> 7;
    __shared__ float sf[32 * NN];
    __shared__ float swx[128 * 33];
    __shared__ float swy[128 * 33];
    float ax[18], ay[18];
#pragma unroll
    for (int n = 0; n < 18; n++) { ax[n] = 0.f; ay[n] = 0.f; }
    const float* fb = g_feats + (size_t)b * MIDD * NN;

    for (int mc = 0; mc < MIDD; mc += 32) {
        int mlen = min(32, MIDD - mc);
        for (int i = t; i < mlen * NN; i += 256) sf[i] = fb[mc * NN + i];
        if (pr == 0) {
            for (int j = 0; j < mlen; j++) swx[h * 33 + j] = wx[(size_t)h * MIDD + mc + j];
        } else {
            for (int j = 0; j < mlen; j++) swy[h * 33 + j] = wy[(size_t)h * MIDD + mc + j];
        }
        __syncthreads();
        for (int j = 0; j < mlen; j++) {
            float wxv = swx[h * 33 + j], wyv = swy[h * 33 + j];
            const float* sr = sf + j * NN + pr * 18;
#pragma unroll
            for (int n = 0; n < 18; n++) {
                float fv = sr[n];
                ax[n] += wxv * fv;
                ay[n] += wyv * fv;
            }
        }
        __syncthreads();
    }
#pragma unroll
    for (int n = 0; n < 18; n++) {
        g_hx[(size_t)b * HIDD * NN + h * NN + pr * 18 + n] = ax[n];
        g_hy[(size_t)b * HIDD * NN + h * NN + pr * 18 + n] = ay[n];
    }
}

// ------------------------- assignment + permutation mix ---------------------
__global__ __launch_bounds__(512) void k_assign(const float* __restrict__ b1,
                                                const float* __restrict__ w2,
                                                const float* __restrict__ b2p,
                                                const float* __restrict__ lrp) {
    int b = blockIdx.x, t = threadIdx.x;
    __shared__ float outS[1296], CSh[1296], LG[1296], PS[1296], DS[1296];
    __shared__ float saS[36], w2S[128], b1S[128];
    if (t < 128) { w2S[t] = w2[t]; b1S[t] = b1[t]; }
    if (t < 36) saS[t] = g_sigatt[b * NN + t];
    __syncthreads();

    const float* hxb = g_hx + (size_t)b * HIDD * NN;
    const float* hyb = g_hy + (size_t)b * HIDD * NN;
    float b2v = b2p[0];

    for (int p = t; p < 1296; p += 512) {
        int i = p / 36, j = p - i * 36;
        float s = 0.f;
#pragma unroll 8
        for (int h = 0; h < HIDD; h++) {
            float v = hxb[h * NN + i] + hyb[h * NN + j] + b1S[h];
            s += w2S[h] * fmaxf(v, 0.f);
        }
        outS[p] = s + b2v;
    }
    __syncthreads();
    for (int p = t; p < 1296; p += 512) {
        int i = p / 36, j = p - i * 36;
        CSh[p] = outS[p] - outS[j * 36 + i];
        LG[p] = 0.f;
    }
    __syncthreads();

    float lrabs = fabsf(lrp[0]);
    for (int it = 0; it < 3; it++) {
        if (t < 36) {
            float mx = -1e30f;
            for (int j = 0; j < 36; j++) mx = fmaxf(mx, LG[t * 36 + j]);
            float sum = 0.f;
            for (int j = 0; j < 36; j++) {
                float e = expf(LG[t * 36 + j] - mx);
                PS[t * 36 + j] = e;
                sum += e;
            }
            float inv = 1.f / sum;
            for (int j = 0; j < 36; j++) PS[t * 36 + j] *= inv;
        }
        __syncthreads();
        if (t < 36) {
            int l = t;
            float tot = 0.f;
            for (int i = 0; i < 36; i++) tot += PS[i * 36 + l];
            float run = 0.f;
            for (int i = 0; i < 36; i++) {
                float p = PS[i * 36 + l];
                run += p;
                DS[i * 36 + l] = tot - 2.f * run + p;
            }
        }
        __syncthreads();
        for (int p = t; p < 1296; p += 512) {
            int i = p / 36, j = p - i * 36;
            float gsum = 0.f;
#pragma unroll
            for (int l = 0; l < 36; l++) gsum += DS[i * 36 + l] * CSh[j * 36 + l];
            LG[p] -= lrabs * gsum;
        }
        __syncthreads();
    }
    if (t < 36) {
        float mx = -1e30f;
        for (int j = 0; j < 36; j++) mx = fmaxf(mx, LG[t * 36 + j]);
        float sum = 0.f;
        for (int j = 0; j < 36; j++) {
            float e = expf(LG[t * 36 + j] - mx);
            PS[t * 36 + j] = e;
            sum += e;
        }
        float inv = 1.f / sum;
        for (int j = 0; j < 36; j++) PS[t * 36 + j] *= inv;
    }
    __syncthreads();

    // x_seq[i][b][c] = sum_l feats[b,c,l]*sig(att)[l]*A[i,l] -> fp16 hi
    const float* fb = g_feats + (size_t)b * MIDD * NN;
    for (int p = t; p < MIDD * NN; p += 512) {
        int c = p / 36, i = p - c * 36;
        float s = 0.f;
#pragma unroll
        for (int l = 0; l < 36; l++) s += fb[c * 36 + l] * saS[l] * PS[i * 36 + l];
        g_xh[((size_t)i * BB + b) * KP2 + c] = __float2half(s);
    }
    for (int p = t; p < (KP2 - MIDD) * NN; p += 512) {
        int c = MIDD + p / 36, i = p % 36;
        g_xh[((size_t)i * BB + b) * KP2 + c] = __float2half(0.f);
    }
}

// ------------------------- launch -------------------------
extern "C" void kernel_launch(void* const* d_in, const int* in_sizes, int n_in,
                              void* d_out, int out_size) {
    const float* boxes     = (const float*)d_in[0];
    const float* attention = (const float*)d_in[1];
    const float* features  = (const float*)d_in[2];
    const float* conv_w    = (const float*)d_in[3];
    const float* conv_b    = (const float*)d_in[4];
    const float* skew_wx   = (const float*)d_in[5];
    const float* skew_wy   = (const float*)d_in[6];
    const float* skew_b1   = (const float*)d_in[7];
    const float* skew_w2   = (const float*)d_in[8];
    const float* skew_b2   = (const float*)d_in[9];
    const float* w_ih      = (const float*)d_in[10];
    const float* w_hh      = (const float*)d_in[11];
    const float* b_ih      = (const float*)d_in[12];
    const float* b_hh      = (const float*)d_in[13];
    const float* lr        = (const float*)d_in[14];

    static int attr_done = 0;
    if (!attr_done) {
        cudaFuncSetAttribute(k_conv, cudaFuncAttributeMaxDynamicSharedMemorySize, C_DYN);
        cudaFuncSetAttribute(k_gin,  cudaFuncAttributeMaxDynamicSharedMemorySize, C_DYN);
        cudaFuncSetAttribute(k_step, cudaFuncAttributeMaxDynamicSharedMemorySize, C_DYN);
        attr_done = 1;
    }

    k_init<<<(BB * OUTD + 255) / 256, 256>>>();
    k_scale<<<1, 128>>>(boxes);
    k_head<<<(BB * NN + 255) / 256, 256>>>(boxes, attention);
    {
        size_t n = (size_t)BB * NN * FEATD;
        k_split_feat<<<(unsigned)((n + 511) / 512), 512>>>(features);
    }
    k_cw<<<(512 * FEATD + 511) / 512, 512>>>(conv_w);
    k_split_wih<<<(G4 * KP2 + 511) / 512, 512>>>(w_ih);
    k_whh<<<(G4 * OUTD + 511) / 512, 512>>>(w_hh);

    k_conv<<<dim3(4, 72), 256, C_DYN>>>(conv_b);
    k_skew<<<BB, 256>>>(skew_wx, skew_wy);
    k_assign<<<BB, 512>>>(skew_b1, skew_w2, skew_b2, lr);
    k_gin<<<dim3(36, 64), 256, C_DYN>>>(b_ih, b_hh);

    for (int s = 0; s < TSTEPS; s++) {
        k_step<<<dim3(2, 64), 256, C_DYN>>>(s, s == TSTEPS - 1 ? (float*)d_out : nullptr);
    }
}